// round 7
// baseline (speedup 1.0000x reference)
#include <cuda_runtime.h>

// Problem constants (fixed shapes for this problem instance)
#define BB 4
#define NV 8192
#define NF 8192
#define NP 2048
#define MIN_DIST 0.1f
#define BIGF 1e10f

#define CHUNK 512           // faces per shared-memory tile
#define NCHUNK (NF / CHUNK) // 16
#define THREADS 128
#define PTS_PER_BLOCK 256   // 2 points per thread
#define PBLOCKS (NP / PTS_PER_BLOCK) // 8

// Scratch (no allocations allowed in kernel_launch)
// Face planes, PAIR-INTERLEAVED layout: for face pair q (faces 2q, 2q+1):
//   g_facep[q*8 + 0,1] = x0,x1   [2,3] = y0,y1   [4,5] = z0,z1   [6,7] = off0,off1
__device__ float        g_facep[BB * NF * 4];
__device__ unsigned int g_minbits[BB * NP]; // unsigned-min of s-bits over all faces

// ---------------------------------------------------------------------------
// f32x2 helpers (Blackwell packed fp32; FFMA2 only reachable via PTX)
// ---------------------------------------------------------------------------
__device__ __forceinline__ unsigned long long fma2(unsigned long long a,
                                                   unsigned long long b,
                                                   unsigned long long c) {
    unsigned long long d;
    asm("fma.rn.f32x2 %0, %1, %2, %3;" : "=l"(d) : "l"(a), "l"(b), "l"(c));
    return d;
}
__device__ __forceinline__ unsigned long long bcast2(float v) {
    unsigned long long d;
    asm("mov.b64 %0, {%1, %1};" : "=l"(d) : "f"(v));
    return d;
}
__device__ __forceinline__ unsigned int umin2(unsigned int a, unsigned int b) {
    return a < b ? a : b; // IMNMX.U32
}

// ---------------------------------------------------------------------------
// Kernel 1: per-face plane precompute (pair-interleaved store) + accum init
// ---------------------------------------------------------------------------
__global__ void prep_kernel(const float* __restrict__ mesh_V,
                            const float* __restrict__ mesh_FN,
                            const int*   __restrict__ mesh_F) {
    int i = blockIdx.x * blockDim.x + threadIdx.x;
    if (i < BB * NP) g_minbits[i] = 0xFFFFFFFFu;
    if (i >= BB * NF) return;

    int b = i / NF;
    int i0 = mesh_F[3 * i + 0];
    int i1 = mesh_F[3 * i + 1];
    int i2 = mesh_F[3 * i + 2];
    const float* Vb = mesh_V + (size_t)b * NV * 3;

    float cx = (Vb[3 * i0 + 0] + Vb[3 * i1 + 0] + Vb[3 * i2 + 0]) * (1.0f / 3.0f);
    float cy = (Vb[3 * i0 + 1] + Vb[3 * i1 + 1] + Vb[3 * i2 + 1]) * (1.0f / 3.0f);
    float cz = (Vb[3 * i0 + 2] + Vb[3 * i1 + 2] + Vb[3 * i2 + 2]) * (1.0f / 3.0f);

    float nx = mesh_FN[3 * i + 0];
    float ny = mesh_FN[3 * i + 1];
    float nz = mesh_FN[3 * i + 2];

    float fnsq = nx * nx + ny * ny + nz * nz;
    float s = sqrtf(fnsq);
    // s' = ||fn|| * (dot(p,fn) - dot(c,fn) + MIN_DIST)  =>  s'^2 == signed^2 * fnsq
    float off = (MIN_DIST - (cx * nx + cy * ny + cz * nz)) * s;

    size_t base = ((size_t)i >> 1) * 8 + (i & 1);
    g_facep[base + 0] = nx * s;
    g_facep[base + 2] = ny * s;
    g_facep[base + 4] = nz * s;
    g_facep[base + 6] = off;
}

// ---------------------------------------------------------------------------
// Kernel 2: main loop. grid = (PBLOCKS, NCHUNK, BB), 128 threads.
// Each thread: 2 points; each f32x2 lane: 2 faces. 4 pairs / 14 warp-instrs.
// Unsigned-min over raw float bits:
//   * nonneg floats sort as unsigned ints -> min works,
//   * negatives (sign bit) sort above ALL nonnegs -> result sign bit set
//     iff every signed distance < 0 (the "all negative => inside" flag).
// ---------------------------------------------------------------------------
__global__ __launch_bounds__(THREADS)
void dist_kernel(const float* __restrict__ points) {
    __shared__ float sf[CHUNK * 4]; // 8 KB, pair-interleaved (x0x1 y0y1 z0z1 w0w1)

    const int b   = blockIdx.z;
    const int tid = threadIdx.x;
    const int p0  = blockIdx.x * PTS_PER_BLOCK + tid;
    const int p1  = p0 + THREADS;

    const float* pp = points + (size_t)b * NP * 3;
    const unsigned long long PX0 = bcast2(pp[3 * p0 + 0]);
    const unsigned long long PY0 = bcast2(pp[3 * p0 + 1]);
    const unsigned long long PZ0 = bcast2(pp[3 * p0 + 2]);
    const unsigned long long PX1 = bcast2(pp[3 * p1 + 0]);
    const unsigned long long PY1 = bcast2(pp[3 * p1 + 1]);
    const unsigned long long PZ1 = bcast2(pp[3 * p1 + 2]);

    // tile copy: CHUNK*4 floats = CHUNK float4s
    {
        const float4* src = (const float4*)(g_facep + (size_t)(b * NF + blockIdx.y * CHUNK) * 4);
        float4* dst = (float4*)sf;
#pragma unroll
        for (int j = tid; j < CHUNK; j += THREADS)
            dst[j] = src[j];
    }
    __syncthreads();

    const unsigned long long* sp = (const unsigned long long*)sf;
    unsigned int m0l = 0xFFFFFFFFu, m0h = 0xFFFFFFFFu;
    unsigned int m1l = 0xFFFFFFFFu, m1h = 0xFFFFFFFFu;

#pragma unroll 4
    for (int q = 0; q < CHUNK / 2; q++) {
        unsigned long long xx = sp[q * 4 + 0];
        unsigned long long yy = sp[q * 4 + 1];
        unsigned long long zz = sp[q * 4 + 2];
        unsigned long long ww = sp[q * 4 + 3];
        unsigned long long s0 = fma2(PX0, xx, fma2(PY0, yy, fma2(PZ0, zz, ww)));
        unsigned long long s1 = fma2(PX1, xx, fma2(PY1, yy, fma2(PZ1, zz, ww)));
        m0l = umin2(m0l, (unsigned int)s0);
        m0h = umin2(m0h, (unsigned int)(s0 >> 32));
        m1l = umin2(m1l, (unsigned int)s1);
        m1h = umin2(m1h, (unsigned int)(s1 >> 32));
    }

    atomicMin(&g_minbits[b * NP + p0], umin2(m0l, m0h));
    atomicMin(&g_minbits[b * NP + p1], umin2(m1l, m1h));
}

// ---------------------------------------------------------------------------
// Kernel 3: finalize -> scalar mean. exterior_flag arrives as int32.
// ---------------------------------------------------------------------------
__global__ void finalize_kernel(const int* __restrict__ ext,
                                float* __restrict__ out) {
    __shared__ float red[256];
    float sum = 0.0f;
    for (int i = threadIdx.x; i < BB * NP; i += 256) {
        unsigned int bits = g_minbits[i];
        // sign bit set => every signed distance was negative => inside
        bool inside = (ext[i] == 0) || (bits & 0x80000000u);
        float m = __uint_as_float(bits);
        sum += inside ? 0.0f : m * m;
    }
    red[threadIdx.x] = sum;
    __syncthreads();
    for (int s = 128; s > 0; s >>= 1) {
        if (threadIdx.x < s) red[threadIdx.x] += red[threadIdx.x + s];
        __syncthreads();
    }
    if (threadIdx.x == 0)
        out[0] = red[0] * (1.0f / (float)(BB * NP));
}

// ---------------------------------------------------------------------------
extern "C" void kernel_launch(void* const* d_in, const int* in_sizes, int n_in,
                              void* d_out, int out_size) {
    const float* mesh_V  = (const float*)d_in[0];
    const float* points  = (const float*)d_in[1];
    const float* mesh_FN = (const float*)d_in[2];
    const int*   mesh_F  = (const int*)d_in[3];
    const int*   exterior = (const int*)d_in[4];
    float* out = (float*)d_out;

    (void)in_sizes; (void)n_in; (void)out_size;

    prep_kernel<<<(BB * NF + 255) / 256, 256>>>(mesh_V, mesh_FN, mesh_F);

    dim3 grid(PBLOCKS, NCHUNK, BB);
    dist_kernel<<<grid, THREADS>>>(points);

    finalize_kernel<<<1, 256>>>(exterior, out);
}